// round 1
// baseline (speedup 1.0000x reference)
#include <cuda_runtime.h>

#define SEQ   2048
#define HD    128
#define NROT  64
#define NROWS (4 * 2048 * 32)   // B*S*n_head = 262144

// Scratch (device globals — allocation-free)
__device__ float  g_G[HD * HD];
__device__ float  g_M[HD * HD];
__device__ float2 g_SC[SEQ * 64];   // (sin, cos) per (pos, freq)

// ---------------------------------------------------------------------------
// Kernel 1: fold the 64 sequential column rotations into G (applied to I).
// Each thread owns one ROW of G -> rows are independent, no syncs needed.
// ---------------------------------------------------------------------------
__global__ void build_G_kernel(const float* __restrict__ thetas,
                               const float* __restrict__ pairs,
                               const float* __restrict__ scale) {
    __shared__ float G[HD][HD + 1];
    int t = threadIdx.x;                       // row index 0..127
    #pragma unroll
    for (int c = 0; c < HD; c++) G[t][c] = (t == c) ? 1.f : 0.f;

    float sc = scale[0];
    for (int k = 0; k < NROT; k++) {
        int   i   = (int)pairs[2 * k];         // trunc toward zero == astype(int32)
        int   j   = (int)pairs[2 * k + 1];
        float th  = thetas[k] * sc;
        float cth = cosf(th), sth = sinf(th);
        float gi = G[t][i], gj = G[t][j];
        if (i == j) {
            G[t][i] = gi * cth;
        } else {
            G[t][i] =  gi * cth + gj * sth;
            G[t][j] = -gi * sth + gj * cth;
        }
    }
    #pragma unroll
    for (int c = 0; c < HD; c++) g_G[t * HD + c] = G[t][c];
}

// ---------------------------------------------------------------------------
// Kernel 2: M = G @ rotation_matrix   (128x128x128, trivial)
// ---------------------------------------------------------------------------
__global__ void build_M_kernel(const float* __restrict__ Rm) {
    __shared__ float gr[HD];
    int row = blockIdx.x, j = threadIdx.x;
    gr[j] = g_G[row * HD + j];
    __syncthreads();
    float acc = 0.f;
    #pragma unroll 8
    for (int k = 0; k < HD; k++) acc += gr[k] * Rm[k * HD + j];
    g_M[row * HD + j] = acc;
}

// ---------------------------------------------------------------------------
// Kernel 3: RoPE sin/cos table: g_SC[s*64+d] = (sin(s*f_d), cos(s*f_d))
// ---------------------------------------------------------------------------
__global__ void build_SC_kernel(const float* __restrict__ inv_freq) {
    int idx = blockIdx.x * blockDim.x + threadIdx.x;
    if (idx < SEQ * 64) {
        int s = idx >> 6, d = idx & 63;
        float a = (float)s * inv_freq[d];
        g_SC[idx] = make_float2(sinf(a), cosf(a));
    }
}

// ---------------------------------------------------------------------------
// Main kernel: per 128-row tile, y = x @ M (M in SMEM), fused RoPE epilogue.
// 256 threads, each computes an 8x8 micro-tile in registers.
// ---------------------------------------------------------------------------
__global__ void __launch_bounds__(256, 1)
rotary_main(const float* __restrict__ x, float* __restrict__ out) {
    extern __shared__ float smem[];
    float (*As)[HD + 1] = (float (*)[HD + 1])smem;        // [128][129] x-tile
    float*  Bs  = smem + 128 * (HD + 1);                  // [128][128] = M (k-major)
    float2* ssc = (float2*)(Bs + 128 * 128);              // [4][64] sin/cos

    const int tid = threadIdx.x;
    const int g0  = blockIdx.x * 128;                     // first global row

    // Load M into SMEM (16384 floats -> 4096 float4, 16 per thread)
    {
        const float4* m4 = (const float4*)g_M;
        float4*       b4 = (float4*)Bs;
        #pragma unroll
        for (int i = 0; i < 16; i++) b4[tid + i * 256] = m4[tid + i * 256];
    }
    // Load x tile (coalesced 512B per warp per iter), row-major into As
    {
        const float4* x4 = (const float4*)x + (size_t)g0 * 32;
        int r  = tid >> 5;        // 0..7
        int kq = tid & 31;        // float4 index along k
        #pragma unroll
        for (int it = 0; it < 16; it++) {
            float4 v = x4[(size_t)(r + it * 8) * 32 + kq];
            float* dst = &As[r + it * 8][kq * 4];
            dst[0] = v.x; dst[1] = v.y; dst[2] = v.z; dst[3] = v.w;
        }
    }
    // Load sin/cos for the 4 sequence positions this tile covers
    {
        int q = tid >> 6, d = tid & 63;
        int s = (((g0 >> 5) + q) & (SEQ - 1));
        ssc[q * 64 + d] = g_SC[s * 64 + d];
    }
    __syncthreads();

    const int ty = tid >> 4;      // 0..15 : row group
    const int tx = tid & 15;      // 0..15 : col group

    float acc[8][8];
    #pragma unroll
    for (int i = 0; i < 8; i++)
        #pragma unroll
        for (int j = 0; j < 8; j++) acc[i][j] = 0.f;

    const float4* Bs4 = (const float4*)Bs;
    #pragma unroll 4
    for (int k = 0; k < 128; k++) {
        float a[8];
        #pragma unroll
        for (int i = 0; i < 8; i++) a[i] = As[ty * 8 + i][k];
        float4 b0 = Bs4[k * 32 + tx * 2];
        float4 b1 = Bs4[k * 32 + tx * 2 + 1];
        float b[8] = {b0.x, b0.y, b0.z, b0.w, b1.x, b1.y, b1.z, b1.w};
        #pragma unroll
        for (int i = 0; i < 8; i++)
            #pragma unroll
            for (int j = 0; j < 8; j++)
                acc[i][j] += a[i] * b[j];
    }

    // Fused RoPE epilogue: y cols (2d, 2d+1) -> out cols (d, 64+d)
    float4* out4 = (float4*)out;
    #pragma unroll
    for (int i = 0; i < 8; i++) {
        int r = ty * 8 + i;
        int q = r >> 5;                   // which of the 4 seq positions
        float4 lo, hi;
        float* lof = (float*)&lo;
        float* hif = (float*)&hi;
        #pragma unroll
        for (int p = 0; p < 4; p++) {
            float2 sc = ssc[q * 64 + tx * 4 + p];   // (sin, cos)
            float e = acc[i][2 * p];
            float o = acc[i][2 * p + 1];
            lof[p] = e * sc.y - o * sc.x;
            hif[p] = e * sc.x + o * sc.y;
        }
        size_t rowbase = (size_t)(g0 + r) * 32;     // in float4 units
        out4[rowbase + tx]      = lo;
        out4[rowbase + 16 + tx] = hi;
    }
}

// ---------------------------------------------------------------------------
extern "C" void kernel_launch(void* const* d_in, const int* in_sizes, int n_in,
                              void* d_out, int out_size) {
    const float* x        = (const float*)d_in[0];
    const float* thetas   = (const float*)d_in[1];
    const float* pairs    = (const float*)d_in[2];
    const float* scale    = (const float*)d_in[3];
    const float* Rm       = (const float*)d_in[4];
    const float* inv_freq = (const float*)d_in[5];
    float*       out      = (float*)d_out;
    (void)in_sizes; (void)n_in; (void)out_size;

    const int smem_bytes = (128 * (HD + 1) + 128 * 128) * 4 + 4 * 64 * 8; // 133632
    cudaFuncSetAttribute(rotary_main, cudaFuncAttributeMaxDynamicSharedMemorySize,
                         smem_bytes);

    build_G_kernel<<<1, 128>>>(thetas, pairs, scale);
    build_M_kernel<<<HD, HD>>>(Rm);
    build_SC_kernel<<<(SEQ * 64 + 255) / 256, 256>>>(inv_freq);
    rotary_main<<<NROWS / 128, 256, smem_bytes>>>(x, out);
}

// round 2
// speedup vs baseline: 1.0030x; 1.0030x over previous
#include <cuda_runtime.h>

#define SEQ   2048
#define HD    128
#define NROT  64
#define NROWS (4 * 2048 * 32)   // B*S*n_head = 262144

// Scratch (device globals — allocation-free)
__device__ float  g_G[HD * HD];
__device__ float  g_M[HD * HD];
__device__ float2 g_SC[SEQ * 64];   // (sin, cos) per (pos, freq)

// ---------------------------------------------------------------------------
// Kernel 1: fold the 64 sequential column rotations into G (applied to I).
// Each thread owns one ROW of G -> rows are independent, no syncs needed.
// ---------------------------------------------------------------------------
__global__ void build_G_kernel(const float* __restrict__ thetas,
                               const float* __restrict__ pairs,
                               const float* __restrict__ scale) {
    __shared__ float G[HD][HD + 1];
    int t = threadIdx.x;                       // row index 0..127
    #pragma unroll
    for (int c = 0; c < HD; c++) G[t][c] = (t == c) ? 1.f : 0.f;

    float sc = scale[0];
    for (int k = 0; k < NROT; k++) {
        int   i   = (int)pairs[2 * k];         // trunc toward zero == astype(int32)
        int   j   = (int)pairs[2 * k + 1];
        float th  = thetas[k] * sc;
        float cth = cosf(th), sth = sinf(th);
        float gi = G[t][i], gj = G[t][j];
        if (i == j) {
            G[t][i] = gi * cth;
        } else {
            G[t][i] =  gi * cth + gj * sth;
            G[t][j] = -gi * sth + gj * cth;
        }
    }
    #pragma unroll
    for (int c = 0; c < HD; c++) g_G[t * HD + c] = G[t][c];
}

// ---------------------------------------------------------------------------
// Kernel 2: M = G @ rotation_matrix   (128x128x128, trivial)
// ---------------------------------------------------------------------------
__global__ void build_M_kernel(const float* __restrict__ Rm) {
    __shared__ float gr[HD];
    int row = blockIdx.x, j = threadIdx.x;
    gr[j] = g_G[row * HD + j];
    __syncthreads();
    float acc = 0.f;
    #pragma unroll 8
    for (int k = 0; k < HD; k++) acc += gr[k] * Rm[k * HD + j];
    g_M[row * HD + j] = acc;
}

// ---------------------------------------------------------------------------
// Kernel 3: RoPE sin/cos table: g_SC[s*64+d] = (sin(s*f_d), cos(s*f_d))
// ---------------------------------------------------------------------------
__global__ void build_SC_kernel(const float* __restrict__ inv_freq) {
    int idx = blockIdx.x * blockDim.x + threadIdx.x;
    if (idx < SEQ * 64) {
        int s = idx >> 6, d = idx & 63;
        float a = (float)s * inv_freq[d];
        g_SC[idx] = make_float2(sinf(a), cosf(a));
    }
}

// ---------------------------------------------------------------------------
// Main kernel: per 128-row tile, y = x @ M (M in SMEM), fused RoPE epilogue.
// 256 threads, each computes an 8x8 micro-tile in registers.
// ---------------------------------------------------------------------------
__global__ void __launch_bounds__(256, 1)
rotary_main(const float* __restrict__ x, float* __restrict__ out) {
    extern __shared__ float smem[];
    float (*As)[HD + 1] = (float (*)[HD + 1])smem;        // [128][129] x-tile
    float*  Bs  = smem + 128 * (HD + 1);                  // [128][128] = M (k-major)
    float2* ssc = (float2*)(Bs + 128 * 128);              // [4][64] sin/cos

    const int tid = threadIdx.x;
    const int g0  = blockIdx.x * 128;                     // first global row

    // Load M into SMEM (16384 floats -> 4096 float4, 16 per thread)
    {
        const float4* m4 = (const float4*)g_M;
        float4*       b4 = (float4*)Bs;
        #pragma unroll
        for (int i = 0; i < 16; i++) b4[tid + i * 256] = m4[tid + i * 256];
    }
    // Load x tile (coalesced 512B per warp per iter), row-major into As
    {
        const float4* x4 = (const float4*)x + (size_t)g0 * 32;
        int r  = tid >> 5;        // 0..7
        int kq = tid & 31;        // float4 index along k
        #pragma unroll
        for (int it = 0; it < 16; it++) {
            float4 v = x4[(size_t)(r + it * 8) * 32 + kq];
            float* dst = &As[r + it * 8][kq * 4];
            dst[0] = v.x; dst[1] = v.y; dst[2] = v.z; dst[3] = v.w;
        }
    }
    // Load sin/cos for the 4 sequence positions this tile covers
    {
        int q = tid >> 6, d = tid & 63;
        int s = (((g0 >> 5) + q) & (SEQ - 1));
        ssc[q * 64 + d] = g_SC[s * 64 + d];
    }
    __syncthreads();

    const int ty = tid >> 4;      // 0..15 : row group
    const int tx = tid & 15;      // 0..15 : col group

    float acc[8][8];
    #pragma unroll
    for (int i = 0; i < 8; i++)
        #pragma unroll
        for (int j = 0; j < 8; j++) acc[i][j] = 0.f;

    const float4* Bs4 = (const float4*)Bs;
    #pragma unroll 4
    for (int k = 0; k < 128; k++) {
        float a[8];
        #pragma unroll
        for (int i = 0; i < 8; i++) a[i] = As[ty * 8 + i][k];
        float4 b0 = Bs4[k * 32 + tx * 2];
        float4 b1 = Bs4[k * 32 + tx * 2 + 1];
        float b[8] = {b0.x, b0.y, b0.z, b0.w, b1.x, b1.y, b1.z, b1.w};
        #pragma unroll
        for (int i = 0; i < 8; i++)
            #pragma unroll
            for (int j = 0; j < 8; j++)
                acc[i][j] += a[i] * b[j];
    }

    // Fused RoPE epilogue: y cols (2d, 2d+1) -> out cols (d, 64+d)
    float4* out4 = (float4*)out;
    #pragma unroll
    for (int i = 0; i < 8; i++) {
        int r = ty * 8 + i;
        int q = r >> 5;                   // which of the 4 seq positions
        float4 lo, hi;
        float* lof = (float*)&lo;
        float* hif = (float*)&hi;
        #pragma unroll
        for (int p = 0; p < 4; p++) {
            float2 sc = ssc[q * 64 + tx * 4 + p];   // (sin, cos)
            float e = acc[i][2 * p];
            float o = acc[i][2 * p + 1];
            lof[p] = e * sc.y - o * sc.x;
            hif[p] = e * sc.x + o * sc.y;
        }
        size_t rowbase = (size_t)(g0 + r) * 32;     // in float4 units
        out4[rowbase + tx]      = lo;
        out4[rowbase + 16 + tx] = hi;
    }
}

// ---------------------------------------------------------------------------
extern "C" void kernel_launch(void* const* d_in, const int* in_sizes, int n_in,
                              void* d_out, int out_size) {
    const float* x        = (const float*)d_in[0];
    const float* thetas   = (const float*)d_in[1];
    const float* pairs    = (const float*)d_in[2];
    const float* scale    = (const float*)d_in[3];
    const float* Rm       = (const float*)d_in[4];
    const float* inv_freq = (const float*)d_in[5];
    float*       out      = (float*)d_out;
    (void)in_sizes; (void)n_in; (void)out_size;

    const int smem_bytes = (128 * (HD + 1) + 128 * 128) * 4 + 4 * 64 * 8; // 133632
    cudaFuncSetAttribute(rotary_main, cudaFuncAttributeMaxDynamicSharedMemorySize,
                         smem_bytes);

    build_G_kernel<<<1, 128>>>(thetas, pairs, scale);
    build_M_kernel<<<HD, HD>>>(Rm);
    build_SC_kernel<<<(SEQ * 64 + 255) / 256, 256>>>(inv_freq);
    rotary_main<<<NROWS / 128, 256, smem_bytes>>>(x, out);
}

// round 4
// speedup vs baseline: 1.7800x; 1.7747x over previous
#include <cuda_runtime.h>
#include <cuda_bf16.h>
#include <cstdint>

#define SEQ   2048
#define HD    128
#define NROT  64
#define NROWS (4 * 2048 * 32)     // 262144 rows of 128
#define TILES (NROWS / 128)       // 2048
#define GRID  152

// SMEM layout (bytes)
#define SMEM_B    0               // 64KB: B fragments (hi then lo), mma frag order
#define SMEM_A    65536           // 2 bufs x 64KB (hi 32KB + lo 32KB each)
#define SMEM_SC   196608          // 256 float2 = 2KB
#define SMEM_SZ   198656

// ---------------- device globals (allocation-free scratch) ----------------
__device__ float  g_G[HD * HD];
__device__ float  g_M[HD * HD];
__device__ float2 g_SC[SEQ * 64];            // (sin, cos)
__device__ uint2  g_Bfrag[2 * 8 * 16 * 32];  // [hl][kt][nt][lane] -> (b0,b1)

// ---------------- helpers ----------------
__device__ __forceinline__ uint32_t smem_u32(const void* p) {
    uint32_t a;
    asm("{ .reg .u64 t; cvta.to.shared.u64 t, %1; cvt.u32.u64 %0, t; }" : "=r"(a) : "l"(p));
    return a;
}

#define LDMATRIX_X4(r, addr) \
    asm volatile("ldmatrix.sync.aligned.m8n8.x4.shared.b16 {%0,%1,%2,%3}, [%4];" \
        : "=r"((r)[0]), "=r"((r)[1]), "=r"((r)[2]), "=r"((r)[3]) : "r"(addr))

#define MMA16816(d, a, b0v, b1v) \
    asm volatile("mma.sync.aligned.m16n8k16.row.col.f32.bf16.bf16.f32 " \
        "{%0,%1,%2,%3}, {%4,%5,%6,%7}, {%8,%9}, {%0,%1,%2,%3};" \
        : "+f"((d)[0]), "+f"((d)[1]), "+f"((d)[2]), "+f"((d)[3]) \
        : "r"((a)[0]), "r"((a)[1]), "r"((a)[2]), "r"((a)[3]), "r"(b0v), "r"(b1v))

// ---------------- prep kernels ----------------
__global__ void build_G_kernel(const float* __restrict__ thetas,
                               const float* __restrict__ pairs,
                               const float* __restrict__ scale) {
    __shared__ float G[HD][HD + 1];
    int t = threadIdx.x;
    #pragma unroll
    for (int c = 0; c < HD; c++) G[t][c] = (t == c) ? 1.f : 0.f;
    float sc = scale[0];
    for (int k = 0; k < NROT; k++) {
        int   i   = (int)pairs[2 * k];
        int   j   = (int)pairs[2 * k + 1];
        float th  = thetas[k] * sc;
        float cth = cosf(th), sth = sinf(th);
        float gi = G[t][i], gj = G[t][j];
        if (i == j) { G[t][i] = gi * cth; }
        else { G[t][i] = gi * cth + gj * sth; G[t][j] = -gi * sth + gj * cth; }
    }
    #pragma unroll
    for (int c = 0; c < HD; c++) g_G[t * HD + c] = G[t][c];
}

__global__ void build_M_kernel(const float* __restrict__ Rm) {
    __shared__ float gr[HD];
    int row = blockIdx.x, j = threadIdx.x;
    gr[j] = g_G[row * HD + j];
    __syncthreads();
    float acc = 0.f;
    #pragma unroll 8
    for (int k = 0; k < HD; k++) acc += gr[k] * Rm[k * HD + j];
    g_M[row * HD + j] = acc;
}

// B operand of y = x@M is exactly M (k-major, col index n). Pack into the
// m16n8k16 B-fragment order: [hl][kt][nt_global][lane] -> uint2 (b0,b1).
//   b0 = {M[kt*16+tq*2][n], M[kt*16+tq*2+1][n]},  b1 = same with k+8
//   n = nt*8 + (lane>>2), tq = lane&3
__global__ void pack_Bfrag_kernel() {
    int idx  = blockIdx.x * 256 + threadIdx.x;   // 0..8191
    int lane = idx & 31;
    int nt   = (idx >> 5) & 15;
    int kt   = (idx >> 9) & 7;
    int hl   = idx >> 12;
    int n  = nt * 8 + (lane >> 2);
    int tq = lane & 3;
    uint32_t w[4];
    #pragma unroll
    for (int e = 0; e < 4; e++) {
        int k = kt * 16 + tq * 2 + (e >> 1) * 8 + (e & 1);
        float v = g_M[k * HD + n];
        __nv_bfloat16 h = __float2bfloat16(v);
        if (hl) h = __float2bfloat16(v - __bfloat162float(h));
        w[e] = (uint32_t)*(uint16_t*)&h;
    }
    g_Bfrag[idx] = make_uint2(w[0] | (w[1] << 16), w[2] | (w[3] << 16));
}

__global__ void build_SC_kernel(const float* __restrict__ inv_freq) {
    int idx = blockIdx.x * blockDim.x + threadIdx.x;
    if (idx < SEQ * 64) {
        int s = idx >> 6, d = idx & 63;
        float a = (float)s * inv_freq[d];
        g_SC[idx] = make_float2(sinf(a), cosf(a));
    }
}

// ---------------- main kernel ----------------
// A tile SMEM layout (hi or lo, 32KB): row-major 256B/row, 16B chunks
// XOR-swizzled:  addr(row,k) = row*256 + (((k>>3) ^ (row&7))<<4) + (k&7)*2

__device__ __forceinline__ void convert_store(const float4* __restrict__ xr,
                                              uint32_t abase, int tid) {
    #pragma unroll
    for (int i = 0; i < 16; i++) {
        int g = tid + i * 256;
        float4 v = xr[i];
        int r = g >> 5;
        int c = g & 31;                 // float4 index: k0 = 4c
        uint32_t h01, h23, l01, l23;
        asm("cvt.rn.bf16x2.f32 %0, %1, %2;" : "=r"(h01) : "f"(v.y), "f"(v.x));
        asm("cvt.rn.bf16x2.f32 %0, %1, %2;" : "=r"(h23) : "f"(v.w), "f"(v.z));
        float hx = __uint_as_float(h01 << 16);
        float hy = __uint_as_float(h01 & 0xFFFF0000u);
        float hz = __uint_as_float(h23 << 16);
        float hw = __uint_as_float(h23 & 0xFFFF0000u);
        float lx = v.x - hx, ly = v.y - hy, lz = v.z - hz, lw = v.w - hw;
        asm("cvt.rn.bf16x2.f32 %0, %1, %2;" : "=r"(l01) : "f"(ly), "f"(lx));
        asm("cvt.rn.bf16x2.f32 %0, %1, %2;" : "=r"(l23) : "f"(lw), "f"(lz));
        uint32_t off = ((uint32_t)r << 8) + (((((uint32_t)c >> 1) ^ (r & 7)) & 15) << 4)
                     + ((c & 1) << 3);
        asm volatile("st.shared.v2.b32 [%0], {%1, %2};" :: "r"(abase + off), "r"(h01), "r"(h23));
        asm volatile("st.shared.v2.b32 [%0], {%1, %2};" :: "r"(abase + 32768 + off), "r"(l01), "r"(l23));
    }
}

__global__ void __launch_bounds__(256, 1)
rotary_mma(const float* __restrict__ x, float* __restrict__ out) {
    extern __shared__ char smem[];
    const uint32_t sb = smem_u32(smem);
    const int tid  = threadIdx.x;
    const int bid  = blockIdx.x;
    const int warp = tid >> 5;
    const int lane = tid & 31;
    const int wm   = warp >> 1;          // 0..3 : 32-row strip
    const int wn   = warp & 1;           // 0..1 : 64-col strip
    const int gq   = lane >> 2;          // 0..7
    const int tq   = lane & 3;           // 0..3

    // load B fragments into SMEM (64KB, layout identical to global)
    {
        const float4* src = (const float4*)g_Bfrag;
        float4* dst = (float4*)(smem + SMEM_B);
        #pragma unroll
        for (int i = 0; i < 16; i++) dst[tid + i * 256] = src[tid + i * 256];
    }

    const int nt_tiles = (TILES - bid + GRID - 1) / GRID;
    const float4* x4 = (const float4*)x;
    float4*       o4 = (float4*)out;
    float2*       sc_s = (float2*)(smem + SMEM_SC);
    const uint2*  Bf   = (const uint2*)(smem + SMEM_B);

    // ldmatrix per-thread address pieces
    const int lr = lane & 15;            // row within 16-row mtile
    const int lc = lane >> 4;            // 0/1 : k-halfchunk select
    const uint32_t sw = lr & 7;
    uint32_t rowoff[2];
    rowoff[0] = (uint32_t)(wm * 32 + lr) << 8;
    rowoff[1] = (uint32_t)(wm * 32 + 16 + lr) << 8;

    // prologue: convert tile 0 into A[0]
    {
        float4 xr[16];
        const float4* xs = x4 + (size_t)bid * 4096;
        #pragma unroll
        for (int i = 0; i < 16; i++) xr[i] = xs[tid + i * 256];
        convert_store(xr, sb + SMEM_A, tid);
    }
    __syncthreads();

    for (int it = 0; it < nt_tiles; it++) {
        const int buf  = it & 1;
        const int tile = bid + it * GRID;
        const uint32_t abase = sb + SMEM_A + (uint32_t)buf * 65536;

        // 1) early LDG of next tile (consumed after MMA -> latency hidden)
        float4 xr[16];
        const bool have_next = (it + 1 < nt_tiles);
        if (have_next) {
            const float4* xs = x4 + (size_t)(tile + GRID) * 4096;
            #pragma unroll
            for (int i = 0; i < 16; i++) xr[i] = xs[tid + i * 256];
        }
        // 2) sin/cos table for this tile's 4 sequence positions
        {
            int s = ((tile << 2) + (tid >> 6)) & (SEQ - 1);
            sc_s[tid] = g_SC[s * 64 + (tid & 63)];
        }

        // 3) MMA: acc = xh*Bh + xh*Bl + xl*Bh
        float acc[2][8][4];
        #pragma unroll
        for (int m = 0; m < 2; m++)
            #pragma unroll
            for (int n = 0; n < 8; n++)
                #pragma unroll
                for (int e = 0; e < 4; e++) acc[m][n][e] = 0.f;

        #pragma unroll
        for (int kt = 0; kt < 8; kt++) {
            uint32_t Ah[2][4], Al[2][4];
            const uint32_t choff = ((((uint32_t)(kt * 2 + lc)) ^ sw) & 15) << 4;
            #pragma unroll
            for (int m = 0; m < 2; m++) {
                uint32_t ad = abase + rowoff[m] + choff;
                LDMATRIX_X4(Ah[m], ad);
                LDMATRIX_X4(Al[m], ad + 32768);
            }
            #pragma unroll
            for (int n = 0; n < 8; n++) {
                const int ntg = wn * 8 + n;
                uint2 bh = Bf[(kt * 16 + ntg) * 32 + lane];
                uint2 bl = Bf[((8 + kt) * 16 + ntg) * 32 + lane];
                #pragma unroll
                for (int m = 0; m < 2; m++) {
                    MMA16816(acc[m][n], Ah[m], bh.x, bh.y);
                    MMA16816(acc[m][n], Ah[m], bl.x, bl.y);
                    MMA16816(acc[m][n], Al[m], bh.x, bh.y);
                }
            }
        }
        __syncthreads();        // all A[buf] reads done; sc_s visible

        // 4) RoPE + staged transpose into A[buf] (reused as 128x128 f32)
        {
            float2 scv[8];
            #pragma unroll
            for (int n = 0; n < 8; n++)
                scv[n] = sc_s[wm * 64 + wn * 32 + n * 4 + tq];

            float* stage = (float*)(smem + SMEM_A + (size_t)buf * 65536);
            #pragma unroll
            for (int m = 0; m < 2; m++) {
                #pragma unroll
                for (int h = 0; h < 2; h++) {
                    int row = wm * 32 + m * 16 + h * 8 + gq;
                    int sw2 = row & 7;
                    float* rp = stage + row * 128 + tq;
                    #pragma unroll
                    for (int n = 0; n < 8; n++) {
                        float e = acc[m][n][h * 2];
                        float o = acc[m][n][h * 2 + 1];
                        float s = scv[n].x, c = scv[n].y;
                        int c4 = wn * 8 + n;
                        rp[((c4       ^ sw2) << 2)] = e * c - o * s;   // col d
                        rp[(((16 + c4) ^ sw2) << 2)] = e * s + o * c;  // col 64+d
                    }
                }
            }
        }
        __syncthreads();

        // 5) coalesced copy stage -> out ; convert next tile into A[buf^1]
        {
            const float* stage = (const float*)(smem + SMEM_A + (size_t)buf * 65536);
            float4* od = o4 + (size_t)tile * 4096;
            #pragma unroll
            for (int i = 0; i < 16; i++) {
                int g = tid + i * 256;
                int row = g >> 5, c4 = g & 31;
                od[g] = *(const float4*)&stage[row * 128 + ((c4 ^ (row & 7)) << 2)];
            }
        }
        if (have_next)
            convert_store(xr, sb + SMEM_A + (uint32_t)(buf ^ 1) * 65536, tid);
        __syncthreads();
    }
}

// ---------------- launcher ----------------
extern "C" void kernel_launch(void* const* d_in, const int* in_sizes, int n_in,
                              void* d_out, int out_size) {
    const float* x        = (const float*)d_in[0];
    const float* thetas   = (const float*)d_in[1];
    const float* pairs    = (const float*)d_in[2];
    const float* scale    = (const float*)d_in[3];
    const float* Rm       = (const float*)d_in[4];
    const float* inv_freq = (const float*)d_in[5];
    float*       out      = (float*)d_out;
    (void)in_sizes; (void)n_in; (void)out_size;

    cudaFuncSetAttribute(rotary_mma, cudaFuncAttributeMaxDynamicSharedMemorySize, SMEM_SZ);

    build_G_kernel<<<1, 128>>>(thetas, pairs, scale);
    build_M_kernel<<<HD, HD>>>(Rm);
    pack_Bfrag_kernel<<<32, 256>>>();
    build_SC_kernel<<<(SEQ * 64 + 255) / 256, 256>>>(inv_freq);
    rotary_mma<<<GRID, 256, SMEM_SZ>>>(x, out);
}

// round 5
// speedup vs baseline: 1.8022x; 1.0125x over previous
#include <cuda_runtime.h>
#include <cuda_bf16.h>
#include <cstdint>
#include <math.h>

#define SEQ   2048
#define HD    128
#define NROT  64
#define NROWS (4 * 2048 * 32)     // 262144 rows of 128
#define TILES (NROWS / 128)       // 2048
#define GRID  152

// main-kernel SMEM layout (bytes)
#define SMEM_B    0               // 64KB: B fragments (hi then lo), mma frag order
#define SMEM_A    65536           // 2 bufs x 64KB (hi 32KB + lo 32KB each)
#define SMEM_SC   196608          // 256 float2 = 2KB
#define SMEM_SZ   198656

// ---------------- device globals (allocation-free scratch) ----------------
__device__ uint2 g_Bfrag[2 * 8 * 16 * 32];   // [hl][kt][nt][lane] -> (b0,b1)

// ---------------- helpers ----------------
__device__ __forceinline__ uint32_t smem_u32(const void* p) {
    uint32_t a;
    asm("{ .reg .u64 t; cvta.to.shared.u64 t, %1; cvt.u32.u64 %0, t; }" : "=r"(a) : "l"(p));
    return a;
}

#define LDMATRIX_X4(r, addr) \
    asm volatile("ldmatrix.sync.aligned.m8n8.x4.shared.b16 {%0,%1,%2,%3}, [%4];" \
        : "=r"((r)[0]), "=r"((r)[1]), "=r"((r)[2]), "=r"((r)[3]) : "r"(addr))

#define MMA16816(d, a, b0v, b1v) \
    asm volatile("mma.sync.aligned.m16n8k16.row.col.f32.bf16.bf16.f32 " \
        "{%0,%1,%2,%3}, {%4,%5,%6,%7}, {%8,%9}, {%0,%1,%2,%3};" \
        : "+f"((d)[0]), "+f"((d)[1]), "+f"((d)[2]), "+f"((d)[3]) \
        : "r"((a)[0]), "r"((a)[1]), "r"((a)[2]), "r"((a)[3]), "r"(b0v), "r"(b1v))

// ---------------- fused prep kernel ----------------
// grid = 64 blocks x 256 threads. Every block:
//  1) folds the 64 sequential rotations into G (in SMEM, redundant per block)
//  2) computes M columns n = 2*bid, 2*bid+1   (M = G @ Rm)
//  3) packs those two columns into g_Bfrag (hi + lo bf16, mma B-frag order)
__global__ void prep_kernel(const float* __restrict__ thetas,
                            const float* __restrict__ pairs,
                            const float* __restrict__ scale,
                            const float* __restrict__ Rm) {
    extern __shared__ float ps[];
    float (*G)[HD + 1] = (float (*)[HD + 1])ps;        // [128][129]
    float (*Mc)[2]     = (float (*)[2])(ps + 128 * (HD + 1));  // [128][2]

    const int tid = threadIdx.x;

    if (tid < 128) {
        const int t = tid;
        #pragma unroll
        for (int c = 0; c < HD; c++) G[t][c] = (t == c) ? 1.f : 0.f;
        float sc = scale[0];
        for (int k = 0; k < NROT; k++) {
            int   i   = (int)pairs[2 * k];
            int   j   = (int)pairs[2 * k + 1];
            float th  = thetas[k] * sc;
            float cth = cosf(th), sth = sinf(th);
            float gi = G[t][i], gj = G[t][j];
            if (i == j) { G[t][i] = gi * cth; }
            else { G[t][i] = gi * cth + gj * sth; G[t][j] = -gi * sth + gj * cth; }
        }
    }
    __syncthreads();

    // M column: thread tid -> k = tid>>1, nl = tid&1, n = 2*bid + nl
    {
        const int k  = tid >> 1;
        const int nl = tid & 1;
        const int n  = blockIdx.x * 2 + nl;
        float acc = 0.f;
        #pragma unroll 8
        for (int j = 0; j < HD; j++) acc += G[k][j] * Rm[j * HD + n];
        Mc[k][nl] = acc;
    }
    __syncthreads();

    // pack: 128 entries per block (2 n x 2 hl x 8 kt x 4 tq)
    if (tid < 128) {
        const int nl  = tid >> 6;
        const int hl  = (tid >> 5) & 1;
        const int kt  = (tid >> 2) & 7;
        const int tq  = tid & 3;
        const int n   = blockIdx.x * 2 + nl;
        const int nt  = n >> 3;
        const int lane = (n & 7) * 4 + tq;
        const int k0  = kt * 16 + tq * 2;
        uint32_t w[4];
        #pragma unroll
        for (int e = 0; e < 4; e++) {
            float v = Mc[k0 + (e >> 1) * 8 + (e & 1)][nl];
            __nv_bfloat16 h = __float2bfloat16(v);
            if (hl) h = __float2bfloat16(v - __bfloat162float(h));
            w[e] = (uint32_t)*(uint16_t*)&h;
        }
        g_Bfrag[((hl * 8 + kt) * 16 + nt) * 32 + lane] =
            make_uint2(w[0] | (w[1] << 16), w[2] | (w[3] << 16));
    }
}

// ---------------- main kernel ----------------
// A tile SMEM layout (hi or lo, 32KB): row-major 256B/row, 16B chunks
// XOR-swizzled:  addr(row,k) = row*256 + (((k>>3) ^ (row&7))<<4) + (k&7)*2

__device__ __forceinline__ void convert_one(float4 v, int g, uint32_t abase) {
    int r = g >> 5;
    int c = g & 31;
    uint32_t h01, h23, l01, l23;
    asm("cvt.rn.bf16x2.f32 %0, %1, %2;" : "=r"(h01) : "f"(v.y), "f"(v.x));
    asm("cvt.rn.bf16x2.f32 %0, %1, %2;" : "=r"(h23) : "f"(v.w), "f"(v.z));
    float hx = __uint_as_float(h01 << 16);
    float hy = __uint_as_float(h01 & 0xFFFF0000u);
    float hz = __uint_as_float(h23 << 16);
    float hw = __uint_as_float(h23 & 0xFFFF0000u);
    float lx = v.x - hx, ly = v.y - hy, lz = v.z - hz, lw = v.w - hw;
    asm("cvt.rn.bf16x2.f32 %0, %1, %2;" : "=r"(l01) : "f"(ly), "f"(lx));
    asm("cvt.rn.bf16x2.f32 %0, %1, %2;" : "=r"(l23) : "f"(lw), "f"(lz));
    uint32_t off = ((uint32_t)r << 8) + (((((uint32_t)c >> 1) ^ (r & 7)) & 15) << 4)
                 + ((c & 1) << 3);
    asm volatile("st.shared.v2.b32 [%0], {%1, %2};" :: "r"(abase + off), "r"(h01), "r"(h23));
    asm volatile("st.shared.v2.b32 [%0], {%1, %2};" :: "r"(abase + 32768 + off), "r"(l01), "r"(l23));
}

__global__ void __launch_bounds__(256, 1)
rotary_mma(const float* __restrict__ x, float* __restrict__ out,
           const float* __restrict__ inv_freq) {
    extern __shared__ char smem[];
    const uint32_t sb = smem_u32(smem);
    const int tid  = threadIdx.x;
    const int bid  = blockIdx.x;
    const int warp = tid >> 5;
    const int lane = tid & 31;
    const int wm   = warp >> 1;          // 0..3 : 32-row strip
    const int wn   = warp & 1;           // 0..1 : 64-col strip
    const int gq   = lane >> 2;          // 0..7
    const int tq   = lane & 3;           // 0..3

    // load B fragments into SMEM (64KB)
    {
        const float4* src = (const float4*)g_Bfrag;
        float4* dst = (float4*)(smem + SMEM_B);
        #pragma unroll
        for (int i = 0; i < 16; i++) dst[tid + i * 256] = src[tid + i * 256];
    }

    const int nt_tiles = (TILES - bid + GRID - 1) / GRID;
    const float4* x4 = (const float4*)x;
    float4*       o4 = (float4*)out;
    float2*       sc_s = (float2*)(smem + SMEM_SC);
    const uint2*  Bf   = (const uint2*)(smem + SMEM_B);

    // sincos duty of this thread: position slot q = tid>>6, freq d = tid&63
    const int   my_q   = tid >> 6;
    const float my_if  = inv_freq[tid & 63];

    // ldmatrix per-thread address pieces
    const int lr = lane & 15;
    const int lc = lane >> 4;
    const uint32_t sw = lr & 7;
    uint32_t rowoff[2];
    rowoff[0] = (uint32_t)(wm * 32 + lr) << 8;
    rowoff[1] = (uint32_t)(wm * 32 + 16 + lr) << 8;

    // prologue: convert tile 0 into A[0]
    {
        const float4* xs = x4 + (size_t)bid * 4096;
        #pragma unroll
        for (int i = 0; i < 16; i++) convert_one(xs[tid + i * 256], tid + i * 256, sb + SMEM_A);
    }
    __syncthreads();

    for (int it = 0; it < nt_tiles; it++) {
        const int buf  = it & 1;
        const int tile = bid + it * GRID;
        const uint32_t abase = sb + SMEM_A + (uint32_t)buf * 65536;
        const uint32_t anext = sb + SMEM_A + (uint32_t)(buf ^ 1) * 65536;
        const bool have_next = (it + 1 < nt_tiles);

        // sincos for this tile (visible after the post-MMA sync)
        {
            float ang = (float)((tile * 4 + my_q) & (SEQ - 1)) * my_if;
            float sv, cv;
            sincosf(ang, &sv, &cv);
            sc_s[tid] = make_float2(sv, cv);
        }

        float acc[2][8][4];
        #pragma unroll
        for (int m = 0; m < 2; m++)
            #pragma unroll
            for (int n = 0; n < 8; n++)
                #pragma unroll
                for (int e = 0; e < 4; e++) acc[m][n][e] = 0.f;

        // pipelined next-tile fetch: 8 chunks of 2 float4, convert 4 iters after load
        const float4* xs = x4 + (size_t)(tile + GRID) * 4096;
        float4 q0[8], q1[8];
        if (have_next) {
            #pragma unroll
            for (int c = 0; c < 4; c++) {
                q0[c] = xs[tid + (2 * c) * 256];
                q1[c] = xs[tid + (2 * c + 1) * 256];
            }
        }

        #pragma unroll
        for (int kt = 0; kt < 8; kt++) {
            if (have_next && kt < 4) {
                q0[kt + 4] = xs[tid + (2 * (kt + 4)) * 256];
                q1[kt + 4] = xs[tid + (2 * (kt + 4) + 1) * 256];
            }
            uint32_t Ah[2][4], Al[2][4];
            const uint32_t choff = ((((uint32_t)(kt * 2 + lc)) ^ sw) & 15) << 4;
            #pragma unroll
            for (int m = 0; m < 2; m++) {
                uint32_t ad = abase + rowoff[m] + choff;
                LDMATRIX_X4(Ah[m], ad);
                LDMATRIX_X4(Al[m], ad + 32768);
            }
            #pragma unroll
            for (int n = 0; n < 8; n++) {
                const int ntg = wn * 8 + n;
                uint2 bh = Bf[(kt * 16 + ntg) * 32 + lane];
                uint2 bl = Bf[((8 + kt) * 16 + ntg) * 32 + lane];
                #pragma unroll
                for (int m = 0; m < 2; m++) {
                    MMA16816(acc[m][n], Ah[m], bh.x, bh.y);
                    MMA16816(acc[m][n], Ah[m], bl.x, bl.y);
                    MMA16816(acc[m][n], Al[m], bh.x, bh.y);
                }
            }
            if (have_next) {
                convert_one(q0[kt], tid + (2 * kt) * 256, anext);
                convert_one(q1[kt], tid + (2 * kt + 1) * 256, anext);
            }
        }
        __syncthreads();        // A[buf] reads done; sc_s + A[buf^1] visible

        // RoPE + staged transpose into A[buf] (reused as 128x128 f32)
        {
            float2 scv[8];
            #pragma unroll
            for (int n = 0; n < 8; n++)
                scv[n] = sc_s[wm * 64 + wn * 32 + n * 4 + tq];

            float* stage = (float*)(smem + SMEM_A + (size_t)buf * 65536);
            #pragma unroll
            for (int m = 0; m < 2; m++) {
                #pragma unroll
                for (int h = 0; h < 2; h++) {
                    int row = wm * 32 + m * 16 + h * 8 + gq;
                    int sw2 = row & 7;
                    float* rp = stage + row * 128 + tq;
                    #pragma unroll
                    for (int n = 0; n < 8; n++) {
                        float e = acc[m][n][h * 2];
                        float o = acc[m][n][h * 2 + 1];
                        float s = scv[n].x, c = scv[n].y;
                        int c4 = wn * 8 + n;
                        rp[((c4       ^ sw2) << 2)] = e * c - o * s;   // col d
                        rp[(((16 + c4) ^ sw2) << 2)] = e * s + o * c;  // col 64+d
                    }
                }
            }
        }
        __syncthreads();

        // coalesced copy stage -> out
        {
            const float* stage = (const float*)(smem + SMEM_A + (size_t)buf * 65536);
            float4* od = o4 + (size_t)tile * 4096;
            #pragma unroll
            for (int i = 0; i < 16; i++) {
                int g = tid + i * 256;
                int row = g >> 5, c4 = g & 31;
                od[g] = *(const float4*)&stage[row * 128 + ((c4 ^ (row & 7)) << 2)];
            }
        }
        __syncthreads();   // stage (A[buf]) becomes next iteration's convert target
    }
}

// ---------------- launcher ----------------
extern "C" void kernel_launch(void* const* d_in, const int* in_sizes, int n_in,
                              void* d_out, int out_size) {
    const float* x        = (const float*)d_in[0];
    const float* thetas   = (const float*)d_in[1];
    const float* pairs    = (const float*)d_in[2];
    const float* scale    = (const float*)d_in[3];
    const float* Rm       = (const float*)d_in[4];
    const float* inv_freq = (const float*)d_in[5];
    float*       out      = (float*)d_out;
    (void)in_sizes; (void)n_in; (void)out_size;

    const int prep_smem = (128 * (HD + 1) + 128 * 2) * 4;   // 67072
    cudaFuncSetAttribute(prep_kernel, cudaFuncAttributeMaxDynamicSharedMemorySize, prep_smem);
    cudaFuncSetAttribute(rotary_mma, cudaFuncAttributeMaxDynamicSharedMemorySize, SMEM_SZ);

    prep_kernel<<<64, 256, prep_smem>>>(thetas, pairs, scale, Rm);
    rotary_mma<<<GRID, 256, SMEM_SZ>>>(x, out, inv_freq);
}

// round 6
// speedup vs baseline: 2.2347x; 1.2400x over previous
#include <cuda_runtime.h>
#include <cuda_bf16.h>
#include <cstdint>
#include <math.h>

#define SEQ   2048
#define HD    128
#define NROT  64
#define NROWS (4 * 2048 * 32)     // 262144 rows of 128
#define TILES (NROWS / 128)       // 2048
#define GRID  152
#define NTHREADS 512

// main-kernel SMEM layout (bytes)
#define SMEM_B    0               // 64KB: B fragments (hi then lo), mma frag order
#define SMEM_A    65536           // 2 bufs x 64KB (hi 32KB + lo 32KB each)
#define SMEM_SC   196608          // 256 float2 = 2KB
#define SMEM_SZ   198656

// ---------------- device globals (allocation-free scratch) ----------------
__device__ uint2 g_Bfrag[2 * 8 * 16 * 32];   // [hl][kt][nt][lane] -> (b0,b1)

// ---------------- helpers ----------------
__device__ __forceinline__ uint32_t smem_u32(const void* p) {
    uint32_t a;
    asm("{ .reg .u64 t; cvta.to.shared.u64 t, %1; cvt.u32.u64 %0, t; }" : "=r"(a) : "l"(p));
    return a;
}

#define LDMATRIX_X4(r, addr) \
    asm volatile("ldmatrix.sync.aligned.m8n8.x4.shared.b16 {%0,%1,%2,%3}, [%4];" \
        : "=r"((r)[0]), "=r"((r)[1]), "=r"((r)[2]), "=r"((r)[3]) : "r"(addr))

#define MMA16816(d, a, b0v, b1v) \
    asm volatile("mma.sync.aligned.m16n8k16.row.col.f32.bf16.bf16.f32 " \
        "{%0,%1,%2,%3}, {%4,%5,%6,%7}, {%8,%9}, {%0,%1,%2,%3};" \
        : "+f"((d)[0]), "+f"((d)[1]), "+f"((d)[2]), "+f"((d)[3]) \
        : "r"((a)[0]), "r"((a)[1]), "r"((a)[2]), "r"((a)[3]), "r"(b0v), "r"(b1v))

// ---------------- fused prep kernel ----------------
__global__ void prep_kernel(const float* __restrict__ thetas,
                            const float* __restrict__ pairs,
                            const float* __restrict__ scale,
                            const float* __restrict__ Rm) {
    extern __shared__ float ps[];
    float (*G)[HD + 1] = (float (*)[HD + 1])ps;                 // [128][129]
    float (*Mc)[2]     = (float (*)[2])(ps + 128 * (HD + 1));   // [128][2]
    float* cs = ps + 128 * (HD + 1) + 256;       // cos[64]
    float* sn = cs + 64;                         // sin[64]
    int*   ij = (int*)(sn + 64);                 // i[64], j[64]

    const int tid = threadIdx.x;

    // stage rotation params once (parallel sincos, coalesced LDG)
    if (tid < 64) {
        float th = thetas[tid] * scale[0];
        float s, c;
        sincosf(th, &s, &c);
        cs[tid] = c; sn[tid] = s;
        ij[tid]      = (int)pairs[2 * tid];
        ij[64 + tid] = (int)pairs[2 * tid + 1];
    }
    __syncthreads();

    if (tid < 128) {
        const int t = tid;
        #pragma unroll
        for (int c = 0; c < HD; c++) G[t][c] = (t == c) ? 1.f : 0.f;
        for (int k = 0; k < NROT; k++) {
            int   i   = ij[k];
            int   j   = ij[64 + k];
            float cth = cs[k], sth = sn[k];
            float gi = G[t][i], gj = G[t][j];
            if (i == j) { G[t][i] = gi * cth; }
            else { G[t][i] = gi * cth + gj * sth; G[t][j] = -gi * sth + gj * cth; }
        }
    }
    __syncthreads();

    // M column: thread tid -> k = tid>>1, nl = tid&1, n = 2*bid + nl
    {
        const int k  = tid >> 1;
        const int nl = tid & 1;
        const int n  = blockIdx.x * 2 + nl;
        float acc = 0.f;
        #pragma unroll 8
        for (int j = 0; j < HD; j++) acc += G[k][j] * Rm[j * HD + n];
        Mc[k][nl] = acc;
    }
    __syncthreads();

    // pack: 128 entries per block (2 n x 2 hl x 8 kt x 4 tq)
    if (tid < 128) {
        const int nl  = tid >> 6;
        const int hl  = (tid >> 5) & 1;
        const int kt  = (tid >> 2) & 7;
        const int tq  = tid & 3;
        const int n   = blockIdx.x * 2 + nl;
        const int nt  = n >> 3;
        const int lane = (n & 7) * 4 + tq;
        const int k0  = kt * 16 + tq * 2;
        uint32_t w[4];
        #pragma unroll
        for (int e = 0; e < 4; e++) {
            float v = Mc[k0 + (e >> 1) * 8 + (e & 1)][nl];
            __nv_bfloat16 h = __float2bfloat16(v);
            if (hl) h = __float2bfloat16(v - __bfloat162float(h));
            w[e] = (uint32_t)*(uint16_t*)&h;
        }
        g_Bfrag[((hl * 8 + kt) * 16 + nt) * 32 + lane] =
            make_uint2(w[0] | (w[1] << 16), w[2] | (w[3] << 16));
    }
}

// ---------------- main kernel ----------------
// A tile SMEM layout (hi or lo, 32KB): row-major 256B/row, 16B chunks
// XOR-swizzled:  addr(row,k) = row*256 + (((k>>3) ^ (row&7))<<4) + (k&7)*2

__device__ __forceinline__ void convert_one(float4 v, int g, uint32_t abase) {
    int r = g >> 5;
    int c = g & 31;
    uint32_t h01, h23, l01, l23;
    asm("cvt.rn.bf16x2.f32 %0, %1, %2;" : "=r"(h01) : "f"(v.y), "f"(v.x));
    asm("cvt.rn.bf16x2.f32 %0, %1, %2;" : "=r"(h23) : "f"(v.w), "f"(v.z));
    float hx = __uint_as_float(h01 << 16);
    float hy = __uint_as_float(h01 & 0xFFFF0000u);
    float hz = __uint_as_float(h23 << 16);
    float hw = __uint_as_float(h23 & 0xFFFF0000u);
    float lx = v.x - hx, ly = v.y - hy, lz = v.z - hz, lw = v.w - hw;
    asm("cvt.rn.bf16x2.f32 %0, %1, %2;" : "=r"(l01) : "f"(ly), "f"(lx));
    asm("cvt.rn.bf16x2.f32 %0, %1, %2;" : "=r"(l23) : "f"(lw), "f"(lz));
    uint32_t off = ((uint32_t)r << 8) + (((((uint32_t)c >> 1) ^ (r & 7)) & 15) << 4)
                 + ((c & 1) << 3);
    asm volatile("st.shared.v2.b32 [%0], {%1, %2};" :: "r"(abase + off), "r"(h01), "r"(h23));
    asm volatile("st.shared.v2.b32 [%0], {%1, %2};" :: "r"(abase + 32768 + off), "r"(l01), "r"(l23));
}

__global__ void __launch_bounds__(NTHREADS, 1)
rotary_mma(const float* __restrict__ x, float* __restrict__ out,
           const float* __restrict__ inv_freq) {
    extern __shared__ char smem[];
    const uint32_t sb = smem_u32(smem);
    const int tid  = threadIdx.x;
    const int bid  = blockIdx.x;
    const int warp = tid >> 5;
    const int lane = tid & 31;
    const int wm   = warp >> 2;          // 0..3 : 32-row strip
    const int wn   = warp & 3;           // 0..3 : 32-col strip
    const int gq   = lane >> 2;          // 0..7
    const int tq   = lane & 3;           // 0..3

    // load B fragments into SMEM (64KB)
    {
        const float4* src = (const float4*)g_Bfrag;
        float4* dst = (float4*)(smem + SMEM_B);
        #pragma unroll
        for (int i = 0; i < 8; i++) dst[tid + i * NTHREADS] = src[tid + i * NTHREADS];
    }

    const int nt_tiles = (TILES - bid + GRID - 1) / GRID;
    const float4* x4 = (const float4*)x;
    float4*       o4 = (float4*)out;
    float2*       sc_s = (float2*)(smem + SMEM_SC);
    const uint2*  Bf   = (const uint2*)(smem + SMEM_B);

    // sincos duty (first 256 threads): position slot q = tid>>6, freq d = tid&63
    const int   my_q  = tid >> 6;
    const float my_if = inv_freq[tid & 63];

    // ldmatrix per-thread address pieces
    const int lr = lane & 15;
    const int lc = lane >> 4;
    const uint32_t sw = lr & 7;
    uint32_t rowoff[2];
    rowoff[0] = (uint32_t)(wm * 32 + lr) << 8;
    rowoff[1] = (uint32_t)(wm * 32 + 16 + lr) << 8;

    // prologue: convert tile 0 into A[0]
    {
        const float4* xs = x4 + (size_t)bid * 4096;
        #pragma unroll
        for (int i = 0; i < 8; i++)
            convert_one(xs[tid + i * NTHREADS], tid + i * NTHREADS, sb + SMEM_A);
    }
    __syncthreads();

    for (int it = 0; it < nt_tiles; it++) {
        const int buf  = it & 1;
        const int tile = bid + it * GRID;
        const uint32_t abase = sb + SMEM_A + (uint32_t)buf * 65536;
        const uint32_t anext = sb + SMEM_A + (uint32_t)(buf ^ 1) * 65536;
        const bool have_next = (it + 1 < nt_tiles);

        // sincos for this tile (visible after the post-MMA sync)
        if (tid < 256) {
            float ang = (float)((tile * 4 + my_q) & (SEQ - 1)) * my_if;
            float sv, cv;
            sincosf(ang, &sv, &cv);
            sc_s[tid] = make_float2(sv, cv);
        }

        float acc[2][4][4];
        #pragma unroll
        for (int m = 0; m < 2; m++)
            #pragma unroll
            for (int n = 0; n < 4; n++)
                #pragma unroll
                for (int e = 0; e < 4; e++) acc[m][n][e] = 0.f;

        // pipelined next-tile fetch: 8 float4 per thread
        const float4* xs = x4 + (size_t)(tile + GRID) * 4096;
        float4 q0[8];
        if (have_next) {
            #pragma unroll
            for (int c = 0; c < 4; c++) q0[c] = xs[tid + c * NTHREADS];
        }

        #pragma unroll
        for (int kt = 0; kt < 8; kt++) {
            if (have_next && kt < 4)
                q0[kt + 4] = xs[tid + (kt + 4) * NTHREADS];
            uint32_t Ah[2][4], Al[2][4];
            const uint32_t choff = ((((uint32_t)(kt * 2 + lc)) ^ sw) & 15) << 4;
            #pragma unroll
            for (int m = 0; m < 2; m++) {
                uint32_t ad = abase + rowoff[m] + choff;
                LDMATRIX_X4(Ah[m], ad);
                LDMATRIX_X4(Al[m], ad + 32768);
            }
            #pragma unroll
            for (int n = 0; n < 4; n++) {
                const int ntg = wn * 4 + n;
                uint2 bh = Bf[(kt * 16 + ntg) * 32 + lane];
                uint2 bl = Bf[((8 + kt) * 16 + ntg) * 32 + lane];
                #pragma unroll
                for (int m = 0; m < 2; m++) {
                    MMA16816(acc[m][n], Ah[m], bh.x, bh.y);
                    MMA16816(acc[m][n], Ah[m], bl.x, bl.y);
                    MMA16816(acc[m][n], Al[m], bh.x, bh.y);
                }
            }
            if (have_next)
                convert_one(q0[kt], tid + kt * NTHREADS, anext);
        }
        __syncthreads();        // A[buf] reads done; sc_s + A[buf^1] visible

        // RoPE + staged transpose into A[buf] (reused as 128x128 f32)
        {
            float2 scv[4];
            #pragma unroll
            for (int n = 0; n < 4; n++)
                scv[n] = sc_s[wm * 64 + (wn * 4 + n) * 4 + tq];

            float* stage = (float*)(smem + SMEM_A + (size_t)buf * 65536);
            #pragma unroll
            for (int m = 0; m < 2; m++) {
                #pragma unroll
                for (int h = 0; h < 2; h++) {
                    int row = wm * 32 + m * 16 + h * 8 + gq;
                    int sw2 = row & 7;
                    float* rp = stage + row * 128 + tq;
                    #pragma unroll
                    for (int n = 0; n < 4; n++) {
                        float e = acc[m][n][h * 2];
                        float o = acc[m][n][h * 2 + 1];
                        float s = scv[n].x, c = scv[n].y;
                        int c4 = wn * 4 + n;
                        rp[((c4       ^ sw2) << 2)] = e * c - o * s;   // col d
                        rp[(((16 + c4) ^ sw2) << 2)] = e * s + o * c;  // col 64+d
                    }
                }
            }
        }
        __syncthreads();

        // coalesced copy stage -> out
        {
            const float* stage = (const float*)(smem + SMEM_A + (size_t)buf * 65536);
            float4* od = o4 + (size_t)tile * 4096;
            #pragma unroll
            for (int i = 0; i < 8; i++) {
                int g = tid + i * NTHREADS;
                int row = g >> 5, c4 = g & 31;
                od[g] = *(const float4*)&stage[row * 128 + ((c4 ^ (row & 7)) << 2)];
            }
        }
        __syncthreads();   // stage (A[buf]) becomes next iteration's convert target
    }
}

// ---------------- launcher ----------------
extern "C" void kernel_launch(void* const* d_in, const int* in_sizes, int n_in,
                              void* d_out, int out_size) {
    const float* x        = (const float*)d_in[0];
    const float* thetas   = (const float*)d_in[1];
    const float* pairs    = (const float*)d_in[2];
    const float* scale    = (const float*)d_in[3];
    const float* Rm       = (const float*)d_in[4];
    const float* inv_freq = (const float*)d_in[5];
    float*       out      = (float*)d_out;
    (void)in_sizes; (void)n_in; (void)out_size;

    const int prep_smem = (128 * (HD + 1) + 256 + 128 + 128) * 4;
    cudaFuncSetAttribute(prep_kernel, cudaFuncAttributeMaxDynamicSharedMemorySize, prep_smem);
    cudaFuncSetAttribute(rotary_mma, cudaFuncAttributeMaxDynamicSharedMemorySize, SMEM_SZ);

    prep_kernel<<<64, 256, prep_smem>>>(thetas, pairs, scale, Rm);
    rotary_mma<<<GRID, NTHREADS, SMEM_SZ>>>(x, out, inv_freq);
}